// round 9
// baseline (speedup 1.0000x reference)
#include <cuda_runtime.h>
#include <cuda_fp16.h>
#include <cstdint>

// ---------------- problem constants ----------------
#define NB 64          // batch
#define NSQ 16         // steps
#define NO 31          // real opcodes
#define NOP 32         // padded opcode slots
#define ND 1024        // hidden dim
#define ND4 256        // float4 slices per row
#define NOG 8          // opcodes per GEMM CTA
#define NGRP 4         // opcode groups

// ---------------- GEMM tiling ----------------
#define GN 32                  // N per CTA
#define GK 64                  // halfs per stage along contraction
#define STAGES 4
#define NIT (ND / GK)          // 16 k-stages
#define GEMM_THREADS 256
#define NCTA 128               // 32 n-tiles x 4 groups; single wave (<=148 SMs)

#define BBYTES (NOG * GN * 128)  // 32 KB
#define ABYTES (64 * 128)        // 8 KB
#define STAGE_BYTES (BBYTES + ABYTES)
#define SMEM_TOTAL (STAGES * STAGE_BYTES + 1024)   // 164864 B -> 1 CTA/SM

#define SWZ(x) ((x) ^ (((x) >> 3) & 0x70))

// ---------------- device scratch (static; allocation is forbidden) ------------
__device__ __align__(256) __half g_Kt[(size_t)NOP * ND * ND];  // [o][n][d] fp16 (slot 31 zero)
__device__ __align__(256) __half g_H[NB * ND];                 // fp16 h (A operand)
__device__ __align__(256) float  g_w[NSQ * NB * NOP];          // softmax weights, all steps
__device__ __align__(256) float  g_gate[NSQ * NB];             // sigmoid(gate), all steps
__device__ __align__(256) float  g_P[(size_t)NGRP * NB * ND];  // group partials, 1 MB

// grid barrier state (zero-init; count returns to 0 after every release)
__device__ unsigned g_bar_count;
__device__ unsigned g_bar_release;

// ---------------- PTX helpers (<= sm_90 features; safe for compute_103) -------
__device__ __forceinline__ uint32_t smem_u32(const void* p) {
    uint32_t a;
    asm("{ .reg .u64 t; cvta.to.shared.u64 t, %1; cvt.u32.u64 %0, t; }" : "=r"(a) : "l"(p));
    return a;
}
__device__ __forceinline__ void cp16(uint32_t dst, const void* src) {
    asm volatile("cp.async.cg.shared.global [%0], [%1], 16;\n"
                 :: "r"(dst), "l"((unsigned long long)__cvta_generic_to_global(src)) : "memory");
}
#define CP_COMMIT() asm volatile("cp.async.commit_group;" ::: "memory")
#define CP_WAIT2()  asm volatile("cp.async.wait_group 2;" ::: "memory")
#define CP_WAIT0()  asm volatile("cp.async.wait_group 0;" ::: "memory")

__device__ __forceinline__ void ldm_x4(uint32_t& r0, uint32_t& r1, uint32_t& r2,
                                       uint32_t& r3, uint32_t addr) {
    asm volatile("ldmatrix.sync.aligned.m8n8.x4.shared.b16 {%0,%1,%2,%3}, [%4];"
                 : "=r"(r0), "=r"(r1), "=r"(r2), "=r"(r3) : "r"(addr));
}
__device__ __forceinline__ void ldm_x2(uint32_t& r0, uint32_t& r1, uint32_t addr) {
    asm volatile("ldmatrix.sync.aligned.m8n8.x2.shared.b16 {%0,%1}, [%2];"
                 : "=r"(r0), "=r"(r1) : "r"(addr));
}
__device__ __forceinline__ void mma16816(float* c, uint32_t a0, uint32_t a1,
                                         uint32_t a2, uint32_t a3,
                                         uint32_t b0, uint32_t b1) {
    asm volatile(
        "mma.sync.aligned.m16n8k16.row.col.f32.f16.f16.f32 "
        "{%0,%1,%2,%3}, {%4,%5,%6,%7}, {%8,%9}, {%0,%1,%2,%3};"
        : "+f"(c[0]), "+f"(c[1]), "+f"(c[2]), "+f"(c[3])
        : "r"(a0), "r"(a1), "r"(a2), "r"(a3), "r"(b0), "r"(b1));
}

// Monotonic-release grid barrier, cg-style: fences only in the elected thread.
// All NCTA CTAs co-resident (single wave).
__device__ __forceinline__ void grid_sync(unsigned base, unsigned gen) {
    __syncthreads();
    if (threadIdx.x == 0) {
        __threadfence();   // release this CTA's prior writes
        if (atomicAdd(&g_bar_count, 1u) == NCTA - 1u) {
            atomicExch(&g_bar_count, 0u);
            __threadfence();
            atomicAdd(&g_bar_release, 1u);
        } else {
            while (*(volatile unsigned*)&g_bar_release - base < gen) {}
        }
        __threadfence();   // acquire other CTAs' writes
    }
    __syncthreads();
}

// ============================================================================
// Kernel 1: transpose + convert  K[o][d][n] fp32  ->  g_Kt[o][n][d] fp16
// grid (32, 32, 32), block (32, 8).  Slot o==31: zeros (pad opcode).
// ============================================================================
__global__ void ktrans_kernel(const float* __restrict__ K) {
    __shared__ float tile[32][33];
    const int o = blockIdx.z;
    const int n0 = blockIdx.x * 32;
    const int d0 = blockIdx.y * 32;
    const int tx = threadIdx.x, ty = threadIdx.y;

    __half* dst = g_Kt + ((size_t)o << 20);
    if (o == NO) {
#pragma unroll
        for (int i = 0; i < 4; i++)
            dst[(size_t)(n0 + ty + i * 8) * ND + d0 + tx] = __float2half(0.0f);
        return;
    }
    const float* src = K + ((size_t)o << 20);
#pragma unroll
    for (int i = 0; i < 4; i++) {
        int dl = ty + i * 8;
        tile[dl][tx] = src[(size_t)(d0 + dl) * ND + n0 + tx];
    }
    __syncthreads();
#pragma unroll
    for (int i = 0; i < 4; i++) {
        int nl = ty + i * 8;
        dst[(size_t)(n0 + nl) * ND + d0 + tx] = __float2half(tile[tx][nl]);
    }
}

// ============================================================================
// Kernel 2: precompute softmax weights + gates for ALL steps (h-independent).
// ============================================================================
__global__ void prep_kernel(const float* __restrict__ logits,
                            const float* __restrict__ operands) {
    const int b = blockIdx.x;
    const int tid = threadIdx.x;
#pragma unroll 1
    for (int s = 0; s < NSQ; s++) {
        float l = (tid < NO) ? logits[(b * NSQ + s) * NO + tid] : -1e30f;
        float m = l;
#pragma unroll
        for (int off = 16; off; off >>= 1)
            m = fmaxf(m, __shfl_xor_sync(0xffffffff, m, off));
        float e = (tid < NO) ? expf(l - m) : 0.0f;
        float sm = e;
#pragma unroll
        for (int off = 16; off; off >>= 1)
            sm += __shfl_xor_sync(0xffffffff, sm, off);
        g_w[(s * NB + b) * NOP + tid] = e / sm;   // slot 31 -> 0
        if (tid == 0)
            g_gate[s * NB + b] =
                1.0f / (1.0f + expf(-operands[(b * NSQ + s) * 4 + 3]));
    }
}

// ============================================================================
// Kernel 3: persistent fused scan.  grid 128, 256 threads, ~161 KB smem.
// Per step: packed 8-op GEMM -> epilogue partials -> [prefetch next B stages]
// -> barrier -> inline gated update -> barrier -> [prefetch A stages].
// ============================================================================
__global__ void __launch_bounds__(GEMM_THREADS, 1)
persist_kernel(const float* __restrict__ signal, float* __restrict__ out) {
    extern __shared__ char smem_raw[];
    const uint32_t sb = (smem_u32(smem_raw) + 1023u) & ~1023u;
    const int tid  = threadIdx.x;
    const int lane = tid & 31;
    const int wid  = tid >> 5;
    const int wm   = wid & 1;    // M 32-half
    const int wn   = wid >> 1;   // N 8-col slice
    const int og   = blockIdx.x >> 5;          // opcode group 0..3
    const int n0   = (blockIdx.x & 31) * GN;   // n-tile 0..992

    const unsigned bar_base = *(volatile unsigned*)&g_bar_release;
    unsigned gen = 0;

    // ---- h slice ownership: thread (cta, tid<128) owns float4 (ob, od4) ----
    const int slice = blockIdx.x * 128 + tid;  // 0..16383
    const int ob  = slice >> 8;
    const int od4 = slice & 255;
    float4 hv = make_float4(0.f, 0.f, 0.f, 0.f);
    if (tid < 128) {
        hv = reinterpret_cast<const float4*>(signal)[ob * ND4 + od4];
        __half2 h01 = __floats2half2_rn(hv.x, hv.y);
        __half2 h23 = __floats2half2_rn(hv.z, hv.w);
        uint2 hh;
        hh.x = *reinterpret_cast<uint32_t*>(&h01);
        hh.y = *reinterpret_cast<uint32_t*>(&h23);
        reinterpret_cast<uint2*>(g_H)[ob * ND4 + od4] = hh;
    }

    const __half* Ksrc = g_Kt + ((size_t)(og * NOG) << 20);

    auto issue_B = [&](int j) {
        const uint32_t base = sb + (j & (STAGES - 1)) * STAGE_BYTES;
        const int kk = j * GK;
#pragma unroll
        for (int i = 0; i < 8; i++) {   // B: 8 ops x 32 rows x 8 x16B
            int idx = tid + i * GEMM_THREADS;
            int op = idx >> 8, row = (idx >> 3) & 31, c = idx & 7;
            cp16(base + op * 4096 + SWZ(row * 128 + c * 16),
                 (const char*)(Ksrc + ((size_t)op << 20) +
                               (size_t)(n0 + row) * ND + kk) + c * 16);
        }
    };
    auto issue_A = [&](int j) {
        const uint32_t abase = sb + (j & (STAGES - 1)) * STAGE_BYTES + BBYTES;
        const int kk = j * GK;
#pragma unroll
        for (int i = 0; i < 2; i++) {   // A: 64 rows x 8 x16B
            int idx = tid + i * GEMM_THREADS;
            int row = idx >> 3, c = idx & 7;
            cp16(abase + SWZ(row * 128 + c * 16),
                 (const char*)(g_H + (size_t)row * ND + kk) + c * 16);
        }
    };

    // step-0 prologue: B prefetch rides through the initial barrier
    issue_B(0); CP_COMMIT();
    issue_B(1); CP_COMMIT();
    issue_B(2); CP_COMMIT();
    grid_sync(bar_base, ++gen);          // g_H(0) visible
    issue_A(0); CP_COMMIT();
    issue_A(1); CP_COMMIT();
    issue_A(2); CP_COMMIT();

    const int a_row = (lane & 15);
    const int a_kb  = (lane >> 4) * 16;
    const int b_row = (lane & 7);
    const int b_kb  = ((lane >> 3) & 1) * 16;

#pragma unroll 1
    for (int t = 0; t < NSQ; t++) {
        float acc[NOG][2][4];
#pragma unroll
        for (int op = 0; op < NOG; op++)
#pragma unroll
            for (int mi = 0; mi < 2; mi++)
#pragma unroll
                for (int c = 0; c < 4; c++) acc[op][mi][c] = 0.0f;

        // mainloop.  Entering: 6 groups pending (B0,B1,B2,A0,A1,A2).
        // wait_group 2 at iter j guarantees B(j)+A(j) complete (incl. tail
        // where the per-iteration commit is empty).
#pragma unroll 1
        for (int j = 0; j < NIT; j++) {
            CP_WAIT2();
            __syncthreads();
            if (j + STAGES - 1 < NIT) { issue_B(j + STAGES - 1); issue_A(j + STAGES - 1); }
            CP_COMMIT();

            const uint32_t base  = sb + (j & (STAGES - 1)) * STAGE_BYTES;
            const uint32_t abase = base + BBYTES;
#pragma unroll
            for (int kc = 0; kc < 4; kc++) {
                uint32_t a[2][4];
#pragma unroll
                for (int mi = 0; mi < 2; mi++) {
                    int row = wm * 32 + mi * 16 + a_row;
                    ldm_x4(a[mi][0], a[mi][1], a[mi][2], a[mi][3],
                           abase + SWZ(row * 128 + kc * 32 + a_kb));
                }
#pragma unroll
                for (int op = 0; op < NOG; op++) {
                    uint32_t b0, b1;
                    ldm_x2(b0, b1,
                           base + op * 4096 +
                           SWZ((wn * 8 + b_row) * 128 + kc * 32 + b_kb));
                    mma16816(acc[op][0], a[0][0], a[0][1], a[0][2], a[0][3], b0, b1);
                    mma16816(acc[op][1], a[1][0], a[1][1], a[1][2], a[1][3], b0, b1);
                }
            }
            __syncthreads();
        }
        CP_WAIT0();   // drain empties; all smem slots free

        // ---- epilogue: fold step-t softmax weights, write group partials ----
        const int r_base = wm * 32 + (lane >> 2);
        const int cb0    = wn * 8 + (lane & 3) * 2;
        const float* wt = g_w + (size_t)t * NB * NOP;
#pragma unroll
        for (int mi = 0; mi < 2; mi++) {
            const int rA = r_base + mi * 16;
            const int rB = rA + 8;
            const float4 wA0 = *reinterpret_cast<const float4*>(wt + rA * NOP + og * NOG);
            const float4 wA1 = *reinterpret_cast<const float4*>(wt + rA * NOP + og * NOG + 4);
            const float4 wB0 = *reinterpret_cast<const float4*>(wt + rB * NOP + og * NOG);
            const float4 wB1 = *reinterpret_cast<const float4*>(wt + rB * NOP + og * NOG + 4);
            const float wAv[8] = {wA0.x, wA0.y, wA0.z, wA0.w, wA1.x, wA1.y, wA1.z, wA1.w};
            const float wBv[8] = {wB0.x, wB0.y, wB0.z, wB0.w, wB1.x, wB1.y, wB1.z, wB1.w};
            float2 sA = make_float2(0.f, 0.f);
            float2 sB = make_float2(0.f, 0.f);
#pragma unroll
            for (int op = 0; op < NOG; op++) {
                sA.x += wAv[op] * acc[op][mi][0];
                sA.y += wAv[op] * acc[op][mi][1];
                sB.x += wBv[op] * acc[op][mi][2];
                sB.y += wBv[op] * acc[op][mi][3];
            }
            *reinterpret_cast<float2*>(g_P + ((size_t)og * NB + rA) * ND + n0 + cb0) = sA;
            *reinterpret_cast<float2*>(g_P + ((size_t)og * NB + rB) * ND + n0 + cb0) = sB;
        }

        // ---- prefetch next step's B stages BEFORE the barriers (h-independent)
        if (t + 1 < NSQ) {
            issue_B(0); CP_COMMIT();
            issue_B(1); CP_COMMIT();
            issue_B(2); CP_COMMIT();
        }

        grid_sync(bar_base, ++gen);   // partials visible everywhere

        // ---- inline gated update on owner threads ----
        if (tid < 128) {
            const float4* P4 = reinterpret_cast<const float4*>(g_P);
            float4 acc4 = make_float4(0.f, 0.f, 0.f, 0.f);
#pragma unroll
            for (int g = 0; g < NGRP; g++) {
                float4 p = __ldcg(P4 + ((size_t)g * NB + ob) * ND4 + od4);
                acc4.x += p.x; acc4.y += p.y; acc4.z += p.z; acc4.w += p.w;
            }
            const float s  = g_gate[t * NB + ob];
            const float is = 1.0f - s;
            hv.x = s * acc4.x + is * hv.x;
            hv.y = s * acc4.y + is * hv.y;
            hv.z = s * acc4.z + is * hv.z;
            hv.w = s * acc4.w + is * hv.w;
            if (t + 1 < NSQ) {
                __half2 h01 = __floats2half2_rn(hv.x, hv.y);
                __half2 h23 = __floats2half2_rn(hv.z, hv.w);
                uint2 hh;
                hh.x = *reinterpret_cast<uint32_t*>(&h01);
                hh.y = *reinterpret_cast<uint32_t*>(&h23);
                reinterpret_cast<uint2*>(g_H)[ob * ND4 + od4] = hh;
            } else {
                reinterpret_cast<float4*>(out)[ob * ND4 + od4] = hv;
            }
        }

        if (t + 1 < NSQ) {
            grid_sync(bar_base, ++gen);   // g_H(t+1) visible
            issue_A(0); CP_COMMIT();
            issue_A(1); CP_COMMIT();
            issue_A(2); CP_COMMIT();
        }
    }
}

// ============================================================================
// Launch
// ============================================================================
extern "C" void kernel_launch(void* const* d_in, const int* in_sizes, int n_in,
                              void* d_out, int out_size) {
    const float* logits   = (const float*)d_in[0];  // (64,16,31)
    const float* operands = (const float*)d_in[1];  // (64,16,4)
    const float* signal   = (const float*)d_in[2];  // (64,1024)
    const float* kernels  = (const float*)d_in[3];  // (31,1024,1024)
    float* out = (float*)d_out;                     // (64,1024)

    static bool attr_set = false;
    if (!attr_set) {
        cudaFuncSetAttribute(persist_kernel,
                             cudaFuncAttributeMaxDynamicSharedMemorySize, SMEM_TOTAL);
        attr_set = true;
    }

    ktrans_kernel<<<dim3(32, 32, NOP), dim3(32, 8)>>>(kernels);
    prep_kernel<<<NB, 32>>>(logits, operands);
    persist_kernel<<<NCTA, GEMM_THREADS, SMEM_TOTAL>>>(signal, out);
}

// round 12
// speedup vs baseline: 1.0119x; 1.0119x over previous
#include <cuda_runtime.h>
#include <cuda_fp16.h>
#include <cstdint>

// ---------------- problem constants ----------------
#define NB 64          // batch
#define NSQ 16         // steps
#define NO 31          // real opcodes
#define NOP 32         // padded opcode slots
#define ND 1024        // hidden dim
#define NOG 8          // opcodes per GEMM CTA
#define NGRP 4         // opcode groups

// ---------------- GEMM tiling ----------------
#define GN 32                  // N per CTA
#define GK 64                  // d-values per stage
#define STAGES 4
#define NIT (ND / GK)          // 16 k-stages
#define GEMM_THREADS 256       // 8 warps: 2 (M) x 4 (N)

#define BBYTES (NOG * GN * 128)  // 32 KB  B: 8 ops x (64 d-rows x 64B packed 2/row)
#define ABYTES (64 * 128)        // 8 KB   A: 64 rows x 128B
#define STAGE_BYTES (BBYTES + ABYTES)
#define SMEM_TOTAL (STAGES * STAGE_BYTES + 1024)   // 164864 B

#define SWZ(x) ((x) ^ (((x) >> 3) & 0x70))

// ---------------- device scratch (static; allocation is forbidden) ------------
// g_Kh: K converted to fp16, SAME layout as input: [o][d][n]  (slot 31 zero)
__device__ __align__(256) __half g_Kh[(size_t)NOP * ND * ND];  // 64 MB
__device__ __align__(256) __half g_H[NB * ND];                 // fp16 h (A operand)
__device__ __align__(256) float  g_h[NB * ND];                 // fp32 master h
__device__ __align__(256) float  g_w[NSQ * NB * NOP];          // softmax weights, all steps
__device__ __align__(256) float  g_gate[NSQ * NB];             // sigmoid(gate), all steps
__device__ __align__(256) float  g_P[(size_t)NGRP * NB * ND];  // group partials, 1 MB

// ---------------- PTX helpers (<= sm_80 features; safe for compute_103) -------
__device__ __forceinline__ uint32_t smem_u32(const void* p) {
    uint32_t a;
    asm("{ .reg .u64 t; cvta.to.shared.u64 t, %1; cvt.u32.u64 %0, t; }" : "=r"(a) : "l"(p));
    return a;
}
__device__ __forceinline__ void cp16(uint32_t dst, const void* src) {
    asm volatile("cp.async.cg.shared.global [%0], [%1], 16;\n"
                 :: "r"(dst), "l"((unsigned long long)__cvta_generic_to_global(src)) : "memory");
}
#define CP_COMMIT() asm volatile("cp.async.commit_group;" ::: "memory")
#define CP_WAIT2()  asm volatile("cp.async.wait_group 2;" ::: "memory")

__device__ __forceinline__ void ldm_x4(uint32_t& r0, uint32_t& r1, uint32_t& r2,
                                       uint32_t& r3, uint32_t addr) {
    asm volatile("ldmatrix.sync.aligned.m8n8.x4.shared.b16 {%0,%1,%2,%3}, [%4];"
                 : "=r"(r0), "=r"(r1), "=r"(r2), "=r"(r3) : "r"(addr));
}
__device__ __forceinline__ void ldm_x2_trans(uint32_t& r0, uint32_t& r1, uint32_t addr) {
    asm volatile("ldmatrix.sync.aligned.m8n8.x2.trans.shared.b16 {%0,%1}, [%2];"
                 : "=r"(r0), "=r"(r1) : "r"(addr));
}
__device__ __forceinline__ void mma16816(float* c, uint32_t a0, uint32_t a1,
                                         uint32_t a2, uint32_t a3,
                                         uint32_t b0, uint32_t b1) {
    asm volatile(
        "mma.sync.aligned.m16n8k16.row.col.f32.f16.f16.f32 "
        "{%0,%1,%2,%3}, {%4,%5,%6,%7}, {%8,%9}, {%0,%1,%2,%3};"
        : "+f"(c[0]), "+f"(c[1]), "+f"(c[2]), "+f"(c[3])
        : "r"(a0), "r"(a1), "r"(a2), "r"(a3), "r"(b0), "r"(b1));
}

// ============================================================================
// Kernel 1: pure streaming convert  K fp32 -> g_Kh fp16 (identical layout).
// grid 16384 x 256; each thread: 8 halfs (read 32B, write 16B). Slot 31 -> 0.
// ============================================================================
__global__ void kconv_kernel(const float* __restrict__ K) {
    const size_t chunk = (size_t)blockIdx.x * 256 + threadIdx.x;  // 16B out chunk
    const int o = (int)(chunk >> 17);            // 131072 chunks per opcode
    const size_t base8 = chunk * 8;              // half index (== float index)
    uint4 outv;
    if (o < NO) {
        const float4* src = reinterpret_cast<const float4*>(K + base8);
        float4 v0 = src[0];
        float4 v1 = src[1];
        __half2 h0 = __floats2half2_rn(v0.x, v0.y);
        __half2 h1 = __floats2half2_rn(v0.z, v0.w);
        __half2 h2 = __floats2half2_rn(v1.x, v1.y);
        __half2 h3 = __floats2half2_rn(v1.z, v1.w);
        outv.x = *reinterpret_cast<uint32_t*>(&h0);
        outv.y = *reinterpret_cast<uint32_t*>(&h1);
        outv.z = *reinterpret_cast<uint32_t*>(&h2);
        outv.w = *reinterpret_cast<uint32_t*>(&h3);
    } else {
        outv = make_uint4(0, 0, 0, 0);
    }
    *reinterpret_cast<uint4*>(g_Kh + base8) = outv;
}

// ============================================================================
// Kernel 2: precompute softmax weights + gates for ALL steps (h-independent).
// grid 64 x 32.
// ============================================================================
__global__ void prep_kernel(const float* __restrict__ logits,
                            const float* __restrict__ operands) {
    const int b = blockIdx.x;
    const int tid = threadIdx.x;
#pragma unroll 1
    for (int s = 0; s < NSQ; s++) {
        float l = (tid < NO) ? logits[(b * NSQ + s) * NO + tid] : -1e30f;
        float m = l;
#pragma unroll
        for (int off = 16; off; off >>= 1)
            m = fmaxf(m, __shfl_xor_sync(0xffffffff, m, off));
        float e = (tid < NO) ? expf(l - m) : 0.0f;
        float sm = e;
#pragma unroll
        for (int off = 16; off; off >>= 1)
            sm += __shfl_xor_sync(0xffffffff, sm, off);
        g_w[(s * NB + b) * NOP + tid] = e / sm;   // slot 31 -> 0
        if (tid == 0)
            g_gate[s * NB + b] =
                1.0f / (1.0f + expf(-operands[(b * NSQ + s) * 4 + 3]));
    }
}

// ============================================================================
// Kernel 3: update.  grid 256 x 128, one float2 slice per thread (32K threads).
// t==0 : h = signal;  t>0 : h = s*sum_g P[g] + (1-s)*h,  s = gate[t-1]
// t<16 : write g_h + g_H(fp16).  t==16: write d_out.
// ============================================================================
__global__ void u_kernel(const float* __restrict__ signal,
                         float* __restrict__ out, int t) {
    const int g  = blockIdx.x * 128 + threadIdx.x;   // 0..32767
    const int b  = g >> 9;
    const int d2 = g & 511;                          // float2 index in row

    float2 hv;
    if (t == 0) {
        hv = reinterpret_cast<const float2*>(signal)[b * 512 + d2];
    } else {
        const float s  = g_gate[(t - 1) * NB + b];
        const float is = 1.0f - s;
        float2 acc = make_float2(0.f, 0.f);
        const float2* P2 = reinterpret_cast<const float2*>(g_P);
#pragma unroll
        for (int gr = 0; gr < NGRP; gr++) {
            float2 p = P2[((size_t)gr * NB + b) * 512 + d2];
            acc.x += p.x; acc.y += p.y;
        }
        float2 ho = reinterpret_cast<const float2*>(g_h)[b * 512 + d2];
        hv.x = s * acc.x + is * ho.x;
        hv.y = s * acc.y + is * ho.y;
    }

    if (t < NSQ) {
        reinterpret_cast<float2*>(g_h)[b * 512 + d2] = hv;
        __half2 hh = __floats2half2_rn(hv.x, hv.y);
        reinterpret_cast<__half2*>(g_H)[b * 512 + d2] = hh;
    } else {
        reinterpret_cast<float2*>(out)[b * 512 + d2] = hv;
    }
}

// ============================================================================
// Kernel 4: GEMM.  grid (32 n-tiles, 4 op-groups), 256 threads, ~161 KB smem.
// B read from native [o][d][n] layout, fragments via ldmatrix.x2.trans.
// Smem B per op: 32 rows x 128B, each row = two consecutive 64B d-segments,
// SW128 swizzle -> conflict-free LDSM (verified: bits[6:4]^bits[9:7] bijective
// over the 8 rows of each matrix).
//   P[grp][b][n] = sum_{op in grp} w[b,op] * sum_d H[b,d] * K[op,d,n]
// ============================================================================
__global__ void __launch_bounds__(GEMM_THREADS, 1) gemm_kernel(int t) {
    extern __shared__ char smem_raw[];
    const uint32_t sb = (smem_u32(smem_raw) + 1023u) & ~1023u;
    const int tid  = threadIdx.x;
    const int lane = tid & 31;
    const int wid  = tid >> 5;
    const int wm   = wid & 1;    // M 32-half
    const int wn   = wid >> 1;   // N 8-col slice
    const int og   = blockIdx.y;
    const int n0   = blockIdx.x * GN;

    const __half* Ksrc = g_Kh + ((size_t)(og * NOG) << 20);

    auto issue_loads = [&](int j) {
        const uint32_t base  = sb + (j & (STAGES - 1)) * STAGE_BYTES;
        const uint32_t abase = base + BBYTES;
        const int kk = j * GK;
#pragma unroll
        for (int i = 0; i < 8; i++) {   // B: 8 ops x 64 d-rows x 4 x16B = 2048
            int idx = tid + i * GEMM_THREADS;
            int op = idx >> 8, d = (idx >> 2) & 63, c = idx & 3;
            cp16(base + op * 4096 + SWZ((d >> 1) * 128 + (d & 1) * 64 + c * 16),
                 (const char*)(Ksrc + ((size_t)op << 20) +
                               (size_t)(kk + d) * ND + n0) + c * 16);
        }
#pragma unroll
        for (int i = 0; i < 2; i++) {   // A: 64 rows x 8 x16B
            int idx = tid + i * GEMM_THREADS;
            int row = idx >> 3, c = idx & 7;
            cp16(abase + SWZ(row * 128 + c * 16),
                 (const char*)(g_H + (size_t)row * ND + kk) + c * 16);
        }
    };

    float acc[NOG][2][4];
#pragma unroll
    for (int op = 0; op < NOG; op++)
#pragma unroll
        for (int mi = 0; mi < 2; mi++)
#pragma unroll
            for (int c = 0; c < 4; c++) acc[op][mi][c] = 0.0f;

    for (int j = 0; j < STAGES - 1; j++) { issue_loads(j); CP_COMMIT(); }

    // lane-derived ldmatrix address components
    const int a_row = (lane & 15);
    const int a_kb  = (lane >> 4) * 16;
    const int dsel  = lane & 15;   // B: d-row within 16-chunk (lanes 0-15 used)

    for (int j = 0; j < NIT; j++) {
        CP_WAIT2();
        __syncthreads();
        if (j + STAGES - 1 < NIT) issue_loads(j + STAGES - 1);
        CP_COMMIT();

        const uint32_t base  = sb + (j & (STAGES - 1)) * STAGE_BYTES;
        const uint32_t abase = base + BBYTES;
#pragma unroll
        for (int kc = 0; kc < 4; kc++) {   // 4 x k16 per stage
            uint32_t a[2][4];
#pragma unroll
            for (int mi = 0; mi < 2; mi++) {
                int row = wm * 32 + mi * 16 + a_row;
                ldm_x4(a[mi][0], a[mi][1], a[mi][2], a[mi][3],
                       abase + SWZ(row * 128 + kc * 32 + a_kb));
            }
            // B address: d = kc*16 + dsel, packed 2 d-rows per 128B smem row
            const int dloc = kc * 16 + dsel;
            const uint32_t boff =
                SWZ((dloc >> 1) * 128 + (dloc & 1) * 64 + wn * 16);
#pragma unroll
            for (int op = 0; op < NOG; op++) {
                uint32_t b0, b1;
                ldm_x2_trans(b0, b1, base + op * 4096 + boff);
                mma16816(acc[op][0], a[0][0], a[0][1], a[0][2], a[0][3], b0, b1);
                mma16816(acc[op][1], a[1][0], a[1][1], a[1][2], a[1][3], b0, b1);
            }
        }
        __syncthreads();
    }

    // ---- epilogue: fold step-t softmax weights, write group partials ----
    const int r_base = wm * 32 + (lane >> 2);
    const int cb0    = wn * 8 + (lane & 3) * 2;
    const float* wt  = g_w + (size_t)t * NB * NOP;
#pragma unroll
    for (int mi = 0; mi < 2; mi++) {
        const int rA = r_base + mi * 16;
        const int rB = rA + 8;
        const float4 wA0 = *reinterpret_cast<const float4*>(wt + rA * NOP + og * NOG);
        const float4 wA1 = *reinterpret_cast<const float4*>(wt + rA * NOP + og * NOG + 4);
        const float4 wB0 = *reinterpret_cast<const float4*>(wt + rB * NOP + og * NOG);
        const float4 wB1 = *reinterpret_cast<const float4*>(wt + rB * NOP + og * NOG + 4);
        const float wAv[8] = {wA0.x, wA0.y, wA0.z, wA0.w, wA1.x, wA1.y, wA1.z, wA1.w};
        const float wBv[8] = {wB0.x, wB0.y, wB0.z, wB0.w, wB1.x, wB1.y, wB1.z, wB1.w};
        float2 sA = make_float2(0.f, 0.f);
        float2 sB = make_float2(0.f, 0.f);
#pragma unroll
        for (int op = 0; op < NOG; op++) {
            sA.x += wAv[op] * acc[op][mi][0];
            sA.y += wAv[op] * acc[op][mi][1];
            sB.x += wBv[op] * acc[op][mi][2];
            sB.y += wBv[op] * acc[op][mi][3];
        }
        *reinterpret_cast<float2*>(g_P + ((size_t)og * NB + rA) * ND + n0 + cb0) = sA;
        *reinterpret_cast<float2*>(g_P + ((size_t)og * NB + rB) * ND + n0 + cb0) = sB;
    }
}

// ============================================================================
// Launch
// ============================================================================
extern "C" void kernel_launch(void* const* d_in, const int* in_sizes, int n_in,
                              void* d_out, int out_size) {
    const float* logits   = (const float*)d_in[0];  // (64,16,31)
    const float* operands = (const float*)d_in[1];  // (64,16,4)
    const float* signal   = (const float*)d_in[2];  // (64,1024)
    const float* kernels  = (const float*)d_in[3];  // (31,1024,1024)
    float* out = (float*)d_out;                     // (64,1024)

    static bool attr_set = false;
    if (!attr_set) {
        cudaFuncSetAttribute(gemm_kernel, cudaFuncAttributeMaxDynamicSharedMemorySize,
                             SMEM_TOTAL);
        attr_set = true;
    }

    kconv_kernel<<<16384, 256>>>(kernels);
    prep_kernel<<<NB, 32>>>(logits, operands);
    for (int t = 0; t <= NSQ; t++) {
        u_kernel<<<256, 128>>>(signal, out, t);
        if (t < NSQ)
            gemm_kernel<<<dim3(32, NGRP), GEMM_THREADS, SMEM_TOTAL>>>(t);
    }
}

// round 14
// speedup vs baseline: 1.0234x; 1.0113x over previous
#include <cuda_runtime.h>
#include <cuda_fp16.h>
#include <cstdint>

// ---------------- problem constants ----------------
#define NB 64          // batch
#define NSQ 16         // steps
#define NO 31          // real opcodes
#define NOP 32         // padded opcode slots
#define ND 1024        // hidden dim
#define NOG 8          // opcodes per GEMM CTA
#define NWOG 4         // opcodes per warp (NOG/2)
#define NGRP 8         // output partial groups (4 CTA-groups x 2 warp op-halves)

// ---------------- GEMM tiling ----------------
#define GN 32                  // N per CTA
#define GK 64                  // d-values per stage
#define STAGES 4
#define NIT (ND / GK)          // 16 k-stages
#define GEMM_THREADS 512       // 16 warps: 2 (op-half) x 2 (M) x 4 (N)

#define BBYTES (NOG * GN * 128)  // 32 KB  B: 8 ops x (64 d-rows packed 2/128B row)
#define ABYTES (64 * 128)        // 8 KB   A: 64 rows x 128B
#define STAGE_BYTES (BBYTES + ABYTES)
#define SMEM_TOTAL (STAGES * STAGE_BYTES + 1024)   // 164864 B -> 1 CTA/SM

#define SWZ(x) ((x) ^ (((x) >> 3) & 0x70))

// ---------------- device scratch (static; allocation is forbidden) ------------
// g_Kh: K converted to fp16, SAME layout as input: [o][d][n]  (slot 31 zero)
__device__ __align__(256) __half g_Kh[(size_t)NOP * ND * ND];  // 64 MB
__device__ __align__(256) __half g_H[NB * ND];                 // fp16 h (A operand)
__device__ __align__(256) float  g_h[NB * ND];                 // fp32 master h
__device__ __align__(256) float  g_w[NSQ * NB * NOP];          // softmax weights, all steps
__device__ __align__(256) float  g_gate[NSQ * NB];             // sigmoid(gate), all steps
__device__ __align__(256) float  g_P[(size_t)NGRP * NB * ND];  // group partials, 2 MB

// ---------------- PTX helpers (<= sm_80 features; safe for compute_103) -------
__device__ __forceinline__ uint32_t smem_u32(const void* p) {
    uint32_t a;
    asm("{ .reg .u64 t; cvta.to.shared.u64 t, %1; cvt.u32.u64 %0, t; }" : "=r"(a) : "l"(p));
    return a;
}
__device__ __forceinline__ void cp16(uint32_t dst, const void* src) {
    asm volatile("cp.async.cg.shared.global [%0], [%1], 16;\n"
                 :: "r"(dst), "l"((unsigned long long)__cvta_generic_to_global(src)) : "memory");
}
#define CP_COMMIT() asm volatile("cp.async.commit_group;" ::: "memory")
#define CP_WAIT2()  asm volatile("cp.async.wait_group 2;" ::: "memory")

__device__ __forceinline__ void ldm_x4(uint32_t& r0, uint32_t& r1, uint32_t& r2,
                                       uint32_t& r3, uint32_t addr) {
    asm volatile("ldmatrix.sync.aligned.m8n8.x4.shared.b16 {%0,%1,%2,%3}, [%4];"
                 : "=r"(r0), "=r"(r1), "=r"(r2), "=r"(r3) : "r"(addr));
}
__device__ __forceinline__ void ldm_x2_trans(uint32_t& r0, uint32_t& r1, uint32_t addr) {
    asm volatile("ldmatrix.sync.aligned.m8n8.x2.trans.shared.b16 {%0,%1}, [%2];"
                 : "=r"(r0), "=r"(r1) : "r"(addr));
}
__device__ __forceinline__ void mma16816(float* c, uint32_t a0, uint32_t a1,
                                         uint32_t a2, uint32_t a3,
                                         uint32_t b0, uint32_t b1) {
    asm volatile(
        "mma.sync.aligned.m16n8k16.row.col.f32.f16.f16.f32 "
        "{%0,%1,%2,%3}, {%4,%5,%6,%7}, {%8,%9}, {%0,%1,%2,%3};"
        : "+f"(c[0]), "+f"(c[1]), "+f"(c[2]), "+f"(c[3])
        : "r"(a0), "r"(a1), "r"(a2), "r"(a3), "r"(b0), "r"(b1));
}

// ============================================================================
// Kernel 1: pure streaming convert  K fp32 -> g_Kh fp16 (identical layout).
// grid 16384 x 256; each thread: 8 halfs.  Slot 31 -> 0.  (DRAM-floor bound.)
// ============================================================================
__global__ void kconv_kernel(const float* __restrict__ K) {
    const size_t chunk = (size_t)blockIdx.x * 256 + threadIdx.x;
    const int o = (int)(chunk >> 17);
    const size_t base8 = chunk * 8;
    uint4 outv;
    if (o < NO) {
        const float4* src = reinterpret_cast<const float4*>(K + base8);
        float4 v0 = src[0];
        float4 v1 = src[1];
        __half2 h0 = __floats2half2_rn(v0.x, v0.y);
        __half2 h1 = __floats2half2_rn(v0.z, v0.w);
        __half2 h2 = __floats2half2_rn(v1.x, v1.y);
        __half2 h3 = __floats2half2_rn(v1.z, v1.w);
        outv.x = *reinterpret_cast<uint32_t*>(&h0);
        outv.y = *reinterpret_cast<uint32_t*>(&h1);
        outv.z = *reinterpret_cast<uint32_t*>(&h2);
        outv.w = *reinterpret_cast<uint32_t*>(&h3);
    } else {
        outv = make_uint4(0, 0, 0, 0);
    }
    *reinterpret_cast<uint4*>(g_Kh + base8) = outv;
}

// ============================================================================
// Kernel 2: precompute softmax weights + gates for ALL steps (h-independent).
// ============================================================================
__global__ void prep_kernel(const float* __restrict__ logits,
                            const float* __restrict__ operands) {
    const int b = blockIdx.x;
    const int tid = threadIdx.x;
#pragma unroll 1
    for (int s = 0; s < NSQ; s++) {
        float l = (tid < NO) ? logits[(b * NSQ + s) * NO + tid] : -1e30f;
        float m = l;
#pragma unroll
        for (int off = 16; off; off >>= 1)
            m = fmaxf(m, __shfl_xor_sync(0xffffffff, m, off));
        float e = (tid < NO) ? expf(l - m) : 0.0f;
        float sm = e;
#pragma unroll
        for (int off = 16; off; off >>= 1)
            sm += __shfl_xor_sync(0xffffffff, sm, off);
        g_w[(s * NB + b) * NOP + tid] = e / sm;   // slot 31 -> 0
        if (tid == 0)
            g_gate[s * NB + b] =
                1.0f / (1.0f + expf(-operands[(b * NSQ + s) * 4 + 3]));
    }
}

// ============================================================================
// Kernel 3: update.  grid 256 x 128, one float2 slice per thread (32K threads).
// t==0 : h = signal;  t>0 : h = s*sum_{g<8} P[g] + (1-s)*h,  s = gate[t-1]
// ============================================================================
__global__ void u_kernel(const float* __restrict__ signal,
                         float* __restrict__ out, int t) {
    const int g  = blockIdx.x * 128 + threadIdx.x;
    const int b  = g >> 9;
    const int d2 = g & 511;

    float2 hv;
    if (t == 0) {
        hv = reinterpret_cast<const float2*>(signal)[b * 512 + d2];
    } else {
        const float s  = g_gate[(t - 1) * NB + b];
        const float is = 1.0f - s;
        float2 acc = make_float2(0.f, 0.f);
        const float2* P2 = reinterpret_cast<const float2*>(g_P);
#pragma unroll
        for (int gr = 0; gr < NGRP; gr++) {
            float2 p = P2[((size_t)gr * NB + b) * 512 + d2];
            acc.x += p.x; acc.y += p.y;
        }
        float2 ho = reinterpret_cast<const float2*>(g_h)[b * 512 + d2];
        hv.x = s * acc.x + is * ho.x;
        hv.y = s * acc.y + is * ho.y;
    }

    if (t < NSQ) {
        reinterpret_cast<float2*>(g_h)[b * 512 + d2] = hv;
        __half2 hh = __floats2half2_rn(hv.x, hv.y);
        reinterpret_cast<__half2*>(g_H)[b * 512 + d2] = hh;
    } else {
        reinterpret_cast<float2*>(out)[b * 512 + d2] = hv;
    }
}

// ============================================================================
// Kernel 4: GEMM.  grid (32 n-tiles, 4 op-groups), 512 threads, ~161 KB smem.
// 16 warps: wo = op-half (4 ops each), wm = M-half, wn = N 8-col slice.
// One __syncthreads per k-iteration (top barrier orders slot reuse).
//   P[og*2+wo][b][n] = sum_{op in half} w[b,op] * sum_d H[b,d] * K[op,d,n]
// ============================================================================
__global__ void __launch_bounds__(GEMM_THREADS, 1) gemm_kernel(int t) {
    extern __shared__ char smem_raw[];
    const uint32_t sb = (smem_u32(smem_raw) + 1023u) & ~1023u;
    const int tid  = threadIdx.x;
    const int lane = tid & 31;
    const int wid  = tid >> 5;
    const int wn   = wid & 3;          // N 8-col slice
    const int wm   = (wid >> 2) & 1;   // M 32-half
    const int wo   = wid >> 3;         // op half: ops wo*4 .. wo*4+3
    const int og   = blockIdx.y;
    const int n0   = blockIdx.x * GN;

    const __half* Ksrc = g_Kh + ((size_t)(og * NOG) << 20);

    auto issue_loads = [&](int j) {
        const uint32_t base  = sb + (j & (STAGES - 1)) * STAGE_BYTES;
        const uint32_t abase = base + BBYTES;
        const int kk = j * GK;
#pragma unroll
        for (int i = 0; i < 4; i++) {   // B: 8 ops x 64 d x 4 x16B = 2048 chunks
            int idx = tid + i * GEMM_THREADS;
            int op = idx >> 8, d = (idx >> 2) & 63, c = idx & 3;
            cp16(base + op * 4096 + SWZ((d >> 1) * 128 + (d & 1) * 64 + c * 16),
                 (const char*)(Ksrc + ((size_t)op << 20) +
                               (size_t)(kk + d) * ND + n0) + c * 16);
        }
        {                               // A: 64 rows x 8 x16B = 512 chunks
            int row = tid >> 3, c = tid & 7;
            cp16(abase + SWZ(row * 128 + c * 16),
                 (const char*)(g_H + (size_t)row * ND + kk) + c * 16);
        }
    };

    float acc[NWOG][2][4];
#pragma unroll
    for (int op = 0; op < NWOG; op++)
#pragma unroll
        for (int mi = 0; mi < 2; mi++)
#pragma unroll
            for (int c = 0; c < 4; c++) acc[op][mi][c] = 0.0f;

    for (int j = 0; j < STAGES - 1; j++) { issue_loads(j); CP_COMMIT(); }

    const int a_row = (lane & 15);
    const int a_kb  = (lane >> 4) * 16;
    const int dsel  = lane & 15;

#pragma unroll 1
    for (int j = 0; j < NIT; j++) {
        CP_WAIT2();
        __syncthreads();                 // slot j ready; also fences slot reuse
        if (j + STAGES - 1 < NIT) issue_loads(j + STAGES - 1);
        CP_COMMIT();

        const uint32_t base  = sb + (j & (STAGES - 1)) * STAGE_BYTES;
        const uint32_t abase = base + BBYTES;
        const uint32_t bop   = base + wo * (NWOG * 4096);
#pragma unroll
        for (int kc = 0; kc < 4; kc++) {   // 4 x k16 per stage
            uint32_t a[2][4];
#pragma unroll
            for (int mi = 0; mi < 2; mi++) {
                int row = wm * 32 + mi * 16 + a_row;
                ldm_x4(a[mi][0], a[mi][1], a[mi][2], a[mi][3],
                       abase + SWZ(row * 128 + kc * 32 + a_kb));
            }
            const int dloc = kc * 16 + dsel;
            const uint32_t boff =
                SWZ((dloc >> 1) * 128 + (dloc & 1) * 64 + wn * 16);
#pragma unroll
            for (int op = 0; op < NWOG; op++) {
                uint32_t b0, b1;
                ldm_x2_trans(b0, b1, bop + op * 4096 + boff);
                mma16816(acc[op][0], a[0][0], a[0][1], a[0][2], a[0][3], b0, b1);
                mma16816(acc[op][1], a[1][0], a[1][1], a[1][2], a[1][3], b0, b1);
            }
        }
    }

    // ---- epilogue: fold step-t softmax weights (this warp's 4 ops) ----
    const int r_base = wm * 32 + (lane >> 2);
    const int cb0    = wn * 8 + (lane & 3) * 2;
    const int go     = og * 2 + wo;               // output group 0..7
    const float* wt  = g_w + (size_t)t * NB * NOP + og * NOG + wo * NWOG;
#pragma unroll
    for (int mi = 0; mi < 2; mi++) {
        const int rA = r_base + mi * 16;
        const int rB = rA + 8;
        const float4 wA = *reinterpret_cast<const float4*>(wt + rA * NOP);
        const float4 wB = *reinterpret_cast<const float4*>(wt + rB * NOP);
        const float wAv[4] = {wA.x, wA.y, wA.z, wA.w};
        const float wBv[4] = {wB.x, wB.y, wB.z, wB.w};
        float2 sA = make_float2(0.f, 0.f);
        float2 sB = make_float2(0.f, 0.f);
#pragma unroll
        for (int op = 0; op < NWOG; op++) {
            sA.x += wAv[op] * acc[op][mi][0];
            sA.y += wAv[op] * acc[op][mi][1];
            sB.x += wBv[op] * acc[op][mi][2];
            sB.y += wBv[op] * acc[op][mi][3];
        }
        *reinterpret_cast<float2*>(g_P + ((size_t)go * NB + rA) * ND + n0 + cb0) = sA;
        *reinterpret_cast<float2*>(g_P + ((size_t)go * NB + rB) * ND + n0 + cb0) = sB;
    }
}

// ============================================================================
// Launch
// ============================================================================
extern "C" void kernel_launch(void* const* d_in, const int* in_sizes, int n_in,
                              void* d_out, int out_size) {
    const float* logits   = (const float*)d_in[0];  // (64,16,31)
    const float* operands = (const float*)d_in[1];  // (64,16,4)
    const float* signal   = (const float*)d_in[2];  // (64,1024)
    const float* kernels  = (const float*)d_in[3];  // (31,1024,1024)
    float* out = (float*)d_out;                     // (64,1024)

    static bool attr_set = false;
    if (!attr_set) {
        cudaFuncSetAttribute(gemm_kernel, cudaFuncAttributeMaxDynamicSharedMemorySize,
                             SMEM_TOTAL);
        attr_set = true;
    }

    kconv_kernel<<<16384, 256>>>(kernels);
    prep_kernel<<<NB, 32>>>(logits, operands);
    for (int t = 0; t <= NSQ; t++) {
        u_kernel<<<256, 128>>>(signal, out, t);
        if (t < NSQ)
            gemm_kernel<<<dim3(32, NGRP / 2), GEMM_THREADS, SMEM_TOTAL>>>(t);
    }
}